// round 4
// baseline (speedup 1.0000x reference)
#include <cuda_runtime.h>
#include <cstdint>

#define BATCH 2
#define SEQ   2048
#define DIM   1024
#define NST   16
#define DTR   64
#define XD    96   /* dt_rank + 2*N */

#define MROWS (BATCH*SEQ) /* 4096 */

// ---------------- scratch (allocation-free: __device__ globals) ----------------
__device__ float g_xz[(size_t)MROWS * 2 * DIM];   // 33.5 MB
__device__ float g_xc[(size_t)MROWS * DIM];       // 16.8 MB
__device__ float g_xdbl[(size_t)MROWS * XD];      // 1.6 MB
__device__ float g_delta[(size_t)MROWS * DIM];    // 16.8 MB
__device__ float g_yg[(size_t)MROWS * DIM];       // 16.8 MB

// ---------------- helpers ----------------
__device__ __forceinline__ float softplusf(float x) {
    return (x > 20.f) ? x : log1pf(__expf(x));
}

__device__ __forceinline__ uint32_t f2tf32(float x) {
    uint32_t r;
    asm("cvt.rna.tf32.f32 %0, %1;" : "=r"(r) : "f"(x));
    return r;
}

// =====================================================================
// TF32 tensor-core NT GEMM: C = A(MxK) * B(NxK)^T, fp32 accumulate.
// BM=BN=128, BK=32, 8 warps (warp tile 64x32), m16n8k8.
// Register-staged double buffering + k-interleaved smem (LDS.64 frags).
// Requires: M%128==0, N%128==0, K%32==0.
// ACT: 0 = none, 1 = softplus(c + bias[n])
// =====================================================================
template<int ACT>
__global__ void __launch_bounds__(256)
gemm_tf32(const float* __restrict__ A, int lda,
          const float* __restrict__ Bm, int ldb,
          float* __restrict__ C, int ldc,
          const float* __restrict__ bias,
          int M, int N, int K)
{
    constexpr int BM = 128, BN = 128, BK = 32;
    constexpr int PITCH = 40;     // floats per row; stride%32==8 -> conflict-free LDS.64
    constexpr int MT = 4, NT = 4; // warp tile 64 x 32

    __shared__ uint32_t As[BM * PITCH];
    __shared__ uint32_t Bs[BN * PITCH];

    const int tid  = threadIdx.x;
    const int wid  = tid >> 5;
    const int lane = tid & 31;
    const int g    = lane >> 2;   // 0..7
    const int tig  = lane & 3;    // 0..3
    const int wm   = (wid >> 2) * 64;   // 2 warp rows
    const int wn   = (wid & 3) * 32;    // 4 warp cols
    const int m0   = blockIdx.y * BM;
    const int n0   = blockIdx.x * BN;

    // fill mapping: slot s covers (row = s>>2, 8-k group = (s&3)*8); 512 slots, 2 per thread
    const int r0c = (tid) >> 2,        grp0 = (tid & 3) * 8;
    const int r1c = (tid + 256) >> 2,  grp1 = (tid & 3) * 8;

    float4 pa0, pa1, pa2, pa3;   // A prefetch: slot0 (k, k+4), slot1 (k, k+4)
    float4 pb0, pb1, pb2, pb3;   // B prefetch

    auto load_regs = [&](int k0) {
        const float* a0p = A + (size_t)(m0 + r0c) * lda + k0 + grp0;
        const float* a1p = A + (size_t)(m0 + r1c) * lda + k0 + grp1;
        const float* b0p = Bm + (size_t)(n0 + r0c) * ldb + k0 + grp0;
        const float* b1p = Bm + (size_t)(n0 + r1c) * ldb + k0 + grp1;
        pa0 = *reinterpret_cast<const float4*>(a0p);
        pa1 = *reinterpret_cast<const float4*>(a0p + 4);
        pa2 = *reinterpret_cast<const float4*>(a1p);
        pa3 = *reinterpret_cast<const float4*>(a1p + 4);
        pb0 = *reinterpret_cast<const float4*>(b0p);
        pb1 = *reinterpret_cast<const float4*>(b0p + 4);
        pb2 = *reinterpret_cast<const float4*>(b1p);
        pb3 = *reinterpret_cast<const float4*>(b1p + 4);
    };

    // interleave: phys [g+0..g+7] = [k0,k4,k1,k5,k2,k6,k3,k7]
    auto store_smem = [&]() {
        uint4* d;
        d = reinterpret_cast<uint4*>(&As[r0c * PITCH + grp0]);
        d[0] = make_uint4(f2tf32(pa0.x), f2tf32(pa1.x), f2tf32(pa0.y), f2tf32(pa1.y));
        d[1] = make_uint4(f2tf32(pa0.z), f2tf32(pa1.z), f2tf32(pa0.w), f2tf32(pa1.w));
        d = reinterpret_cast<uint4*>(&As[r1c * PITCH + grp1]);
        d[0] = make_uint4(f2tf32(pa2.x), f2tf32(pa3.x), f2tf32(pa2.y), f2tf32(pa3.y));
        d[1] = make_uint4(f2tf32(pa2.z), f2tf32(pa3.z), f2tf32(pa2.w), f2tf32(pa3.w));
        d = reinterpret_cast<uint4*>(&Bs[r0c * PITCH + grp0]);
        d[0] = make_uint4(f2tf32(pb0.x), f2tf32(pb1.x), f2tf32(pb0.y), f2tf32(pb1.y));
        d[1] = make_uint4(f2tf32(pb0.z), f2tf32(pb1.z), f2tf32(pb0.w), f2tf32(pb1.w));
        d = reinterpret_cast<uint4*>(&Bs[r1c * PITCH + grp1]);
        d[0] = make_uint4(f2tf32(pb2.x), f2tf32(pb3.x), f2tf32(pb2.y), f2tf32(pb3.y));
        d[1] = make_uint4(f2tf32(pb2.z), f2tf32(pb3.z), f2tf32(pb2.w), f2tf32(pb3.w));
    };

    float c[MT][NT][4];
#pragma unroll
    for (int i = 0; i < MT; i++)
#pragma unroll
        for (int j = 0; j < NT; j++)
#pragma unroll
            for (int r = 0; r < 4; r++) c[i][j][r] = 0.f;

    auto compute = [&]() {
#pragma unroll
        for (int kk = 0; kk < BK; kk += 8) {
            const int ko = kk + 2 * tig;
            uint2 av0[MT], av1[MT], bv[NT];
#pragma unroll
            for (int mt = 0; mt < MT; mt++) {
                int row = wm + mt * 16 + g;
                av0[mt] = *reinterpret_cast<const uint2*>(&As[row * PITCH + ko]);
                av1[mt] = *reinterpret_cast<const uint2*>(&As[(row + 8) * PITCH + ko]);
            }
#pragma unroll
            for (int nt = 0; nt < NT; nt++) {
                bv[nt] = *reinterpret_cast<const uint2*>(&Bs[(wn + nt * 8 + g) * PITCH + ko]);
            }
#pragma unroll
            for (int mt = 0; mt < MT; mt++)
#pragma unroll
                for (int nt = 0; nt < NT; nt++) {
                    asm volatile(
                        "mma.sync.aligned.m16n8k8.row.col.f32.tf32.tf32.f32 "
                        "{%0,%1,%2,%3}, {%4,%5,%6,%7}, {%8,%9}, {%0,%1,%2,%3};\n"
                        : "+f"(c[mt][nt][0]), "+f"(c[mt][nt][1]),
                          "+f"(c[mt][nt][2]), "+f"(c[mt][nt][3])
                        : "r"(av0[mt].x), "r"(av1[mt].x),
                          "r"(av0[mt].y), "r"(av1[mt].y),
                          "r"(bv[nt].x),  "r"(bv[nt].y));
                }
        }
    };

    load_regs(0);
    store_smem();
    __syncthreads();

    for (int k0 = BK; k0 < K; k0 += BK) {
        load_regs(k0);     // prefetch next tile (LDG overlaps MMAs below)
        compute();
        __syncthreads();
        store_smem();
        __syncthreads();
    }
    compute();

    // ---- epilogue ----
#pragma unroll
    for (int mt = 0; mt < MT; mt++) {
        int r = m0 + wm + mt * 16 + g;
#pragma unroll
        for (int nt = 0; nt < NT; nt++) {
            int n = n0 + wn + nt * 8 + tig * 2;
            float v0 = c[mt][nt][0], v1 = c[mt][nt][1];
            float v2 = c[mt][nt][2], v3 = c[mt][nt][3];
            if (ACT == 1) {
                float b0 = bias[n], b1 = bias[n + 1];
                v0 = softplusf(v0 + b0);  v1 = softplusf(v1 + b1);
                v2 = softplusf(v2 + b0);  v3 = softplusf(v3 + b1);
            }
            *reinterpret_cast<float2*>(C + (size_t)r * ldc + n)       = make_float2(v0, v1);
            *reinterpret_cast<float2*>(C + (size_t)(r + 8) * ldc + n) = make_float2(v2, v3);
        }
    }
}

// ---------------- FFMA NT SGEMM (kept for x_proj, exact fp32) ----------------
template<int BM, int BN, int BK, int TM, int TN>
__global__ void __launch_bounds__((BM/TM)*(BN/TN))
sgemm_nt(const float* __restrict__ A, int lda,
         const float* __restrict__ Bm, int ldb,
         float* __restrict__ C, int ldc,
         int M, int N, int K)
{
    constexpr int THREADS = (BM/TM)*(BN/TN);
    constexpr int A_SLOTS = BM*BK/4;
    constexpr int B_SLOTS = BN*BK/4;

    __shared__ float As[BK][BM];
    __shared__ float Bs[BK][BN];

    const int tid = threadIdx.x;
    const int tx = tid % (BN/TN);
    const int ty = tid / (BN/TN);
    const int m0 = blockIdx.y * BM;
    const int n0 = blockIdx.x * BN;

    float acc[TM][TN];
#pragma unroll
    for (int i = 0; i < TM; i++)
#pragma unroll
        for (int j = 0; j < TN; j++) acc[i][j] = 0.f;

    for (int k0 = 0; k0 < K; k0 += BK) {
#pragma unroll
        for (int it = 0; it < A_SLOTS/THREADS; it++) {
            int s = tid + it*THREADS;
            int row = s / (BK/4);
            int kk  = (s % (BK/4)) * 4;
            float4 v = *reinterpret_cast<const float4*>(
                A + (size_t)(m0 + row) * lda + k0 + kk);
            As[kk+0][row] = v.x; As[kk+1][row] = v.y;
            As[kk+2][row] = v.z; As[kk+3][row] = v.w;
        }
#pragma unroll
        for (int it = 0; it < B_SLOTS/THREADS; it++) {
            int s = tid + it*THREADS;
            int row = s / (BK/4);
            int kk  = (s % (BK/4)) * 4;
            float4 v = make_float4(0.f, 0.f, 0.f, 0.f);
            if (n0 + row < N)
                v = *reinterpret_cast<const float4*>(
                    Bm + (size_t)(n0 + row) * ldb + k0 + kk);
            Bs[kk+0][row] = v.x; Bs[kk+1][row] = v.y;
            Bs[kk+2][row] = v.z; Bs[kk+3][row] = v.w;
        }
        __syncthreads();

#pragma unroll
        for (int kk = 0; kk < BK; kk++) {
            float a[TM], b[TN];
#pragma unroll
            for (int i = 0; i < TM; i += 4) {
                float4 v = *reinterpret_cast<const float4*>(&As[kk][ty*TM + i]);
                a[i+0] = v.x; a[i+1] = v.y; a[i+2] = v.z; a[i+3] = v.w;
            }
#pragma unroll
            for (int j = 0; j < TN; j += 4) {
                float4 v = *reinterpret_cast<const float4*>(&Bs[kk][tx*TN + j]);
                b[j+0] = v.x; b[j+1] = v.y; b[j+2] = v.z; b[j+3] = v.w;
            }
#pragma unroll
            for (int i = 0; i < TM; i++)
#pragma unroll
                for (int j = 0; j < TN; j++)
                    acc[i][j] = fmaf(a[i], b[j], acc[i][j]);
        }
        __syncthreads();
    }

#pragma unroll
    for (int i = 0; i < TM; i++) {
        int m = m0 + ty*TM + i;
#pragma unroll
        for (int j = 0; j < TN; j++) {
            int n = n0 + tx*TN + j;
            if (n < N) C[(size_t)m * ldc + n] = acc[i][j];
        }
    }
}

// ---------------- depthwise conv1d k=3 pad=1 (input = first half of xz) --------
__global__ void conv_kernel(const float* __restrict__ xz,
                            const float* __restrict__ w,
                            const float* __restrict__ bconv,
                            float* __restrict__ xc)
{
    int idx = blockIdx.x * blockDim.x + threadIdx.x;   // over MROWS*DIM
    if (idx >= MROWS * DIM) return;
    int d = idx & (DIM - 1);
    int l = (idx >> 10) & (SEQ - 1);
    const float* base = xz + (size_t)(idx >> 10) * (2*DIM) + d;
    float w0 = w[d*3+0], w1 = w[d*3+1], w2 = w[d*3+2];
    float acc = bconv[d];
    if (l > 0)       acc = fmaf(w0, base[-(2*DIM)], acc);
    acc = fmaf(w1, base[0], acc);
    if (l < SEQ - 1) acc = fmaf(w2, base[2*DIM], acc);
    xc[idx] = acc;
}

// ---------------- selective scan + D skip + SiLU(z) gate -----------------------
// One warp = 2 channels x 16 states. Lanes 0-15: chan0 state n; 16-31: chan1.
__global__ void scan_kernel(const float* __restrict__ delta,
                            const float* __restrict__ u,
                            const float* __restrict__ xdbl,
                            const float* __restrict__ xz,
                            const float* __restrict__ A_log,
                            const float* __restrict__ Dp,
                            float* __restrict__ yg)
{
    const int lane = threadIdx.x & 31;
    const int warp = threadIdx.x >> 5;
    const int n = lane & 15;
    const int chan = blockIdx.x * ((int)blockDim.x >> 4) + (warp << 1) + (lane >> 4);
    const int b = chan >> 10;          // chan / DIM
    const int d = chan & (DIM - 1);

    const float A    = -__expf(__ldg(A_log + d*NST + n));
    const float Dpar = __ldg(Dp + d);

    const size_t row0 = (size_t)b * SEQ;
    const float* pD  = delta + row0 * DIM + d;
    const float* pU  = u     + row0 * DIM + d;
    const float* pBC = xdbl  + row0 * XD;
    const float* pZ  = xz    + row0 * (2*DIM) + DIM + d;
    float*       pY  = yg    + row0 * DIM + d;

    float s = 0.f;
#pragma unroll 2
    for (int t = 0; t < SEQ; ++t) {
        float dt = __ldg(pD);
        float uu = __ldg(pU);
        float Bn = __ldg(pBC + DTR + n);
        float Cn = __ldg(pBC + DTR + NST + n);

        float dA = __expf(dt * A);
        s = fmaf(dA, s, dt * Bn * uu);

        float p = s * Cn;
        p += __shfl_xor_sync(0xffffffffu, p, 1);
        p += __shfl_xor_sync(0xffffffffu, p, 2);
        p += __shfl_xor_sync(0xffffffffu, p, 4);
        p += __shfl_xor_sync(0xffffffffu, p, 8);

        if (n == 0) {
            float z = __ldg(pZ);
            float sig = __fdividef(1.f, 1.f + __expf(-z));
            pY[0] = fmaf(uu, Dpar, p) * (z * sig);
        }
        pD += DIM; pU += DIM; pBC += XD; pZ += 2*DIM; pY += DIM;
    }
}

// ---------------- launcher ----------------
extern "C" void kernel_launch(void* const* d_in, const int* in_sizes, int n_in,
                              void* d_out, int out_size)
{
    const float* x          = (const float*)d_in[0];
    const float* in_proj_w  = (const float*)d_in[1];
    const float* conv_w     = (const float*)d_in[2];
    const float* conv_b     = (const float*)d_in[3];
    const float* A_log      = (const float*)d_in[4];
    const float* D_param    = (const float*)d_in[5];
    const float* x_proj_w   = (const float*)d_in[6];
    const float* dt_proj_w  = (const float*)d_in[7];
    const float* dt_proj_b  = (const float*)d_in[8];
    const float* out_proj_w = (const float*)d_in[9];
    float* out = (float*)d_out;

    float *xz, *xc, *xdbl, *delta, *yg;
    cudaGetSymbolAddress((void**)&xz,    g_xz);
    cudaGetSymbolAddress((void**)&xc,    g_xc);
    cudaGetSymbolAddress((void**)&xdbl,  g_xdbl);
    cudaGetSymbolAddress((void**)&delta, g_delta);
    cudaGetSymbolAddress((void**)&yg,    g_yg);

    const int M = MROWS;

    // 1. in_proj: xz = x @ in_proj_w^T   (4096 x 2048 x 1024)  [tf32 tensor core]
    gemm_tf32<0><<<dim3((2*DIM)/128, M/128), 256>>>(
        x, DIM, in_proj_w, DIM, xz, 2*DIM, nullptr, M, 2*DIM, DIM);

    // 2. depthwise conv1d on first half of xz -> xc
    conv_kernel<<<(M*DIM)/256, 256>>>(xz, conv_w, conv_b, xc);

    // 3. x_proj: xdbl = xc @ x_proj_w^T  (4096 x 96 x 1024)  [exact fp32]
    sgemm_nt<64,64,16,4,4><<<dim3((XD + 63)/64, M/64), 256>>>(
        xc, DIM, x_proj_w, DIM, xdbl, XD, M, XD, DIM);

    // 4. dt_proj + softplus: delta = softplus(xdbl[:, :64] @ dt_proj_w^T + b) [tf32]
    gemm_tf32<1><<<dim3(DIM/128, M/128), 256>>>(
        xdbl, XD, dt_proj_w, DTR, delta, DIM, dt_proj_b, M, DIM, DTR);

    // 5. selective scan + D skip + SiLU(z) gate -> yg
    scan_kernel<<<(BATCH*DIM)/8, 128>>>(delta, xc, xdbl, xz, A_log, D_param, yg);

    // 6. out_proj: out = yg @ out_proj_w^T  (4096 x 1024 x 1024)  [tf32]
    gemm_tf32<0><<<dim3(DIM/128, M/128), 256>>>(
        yg, DIM, out_proj_w, DIM, out, DIM, nullptr, M, DIM, DIM);
}

// round 6
// speedup vs baseline: 1.0032x; 1.0032x over previous
#include <cuda_runtime.h>
#include <cstdint>

#define BATCH 2
#define SEQ   2048
#define DIM   1024
#define NST   16
#define DTR   64
#define XD    96   /* dt_rank + 2*N */

#define MROWS (BATCH*SEQ) /* 4096 */

// ---------------- scratch (allocation-free: __device__ globals) ----------------
__device__ float g_xz[(size_t)MROWS * 2 * DIM];   // 33.5 MB
__device__ float g_xc[(size_t)MROWS * DIM];       // 16.8 MB
__device__ float g_xdbl[(size_t)MROWS * XD];      // 1.6 MB
__device__ float g_delta[(size_t)MROWS * DIM];    // 16.8 MB
__device__ float g_yg[(size_t)MROWS * DIM];       // 16.8 MB (tf32-rounded by scan)
// tf32-rounded operand copies
__device__ float g_xtf[(size_t)MROWS * DIM];      // 16.8 MB
__device__ float g_wtf_in[(size_t)2 * DIM * DIM]; // 8.4 MB
__device__ float g_wtf_out[(size_t)DIM * DIM];    // 4.2 MB
__device__ float g_wtf_dt[(size_t)DIM * DTR];     // 0.26 MB
__device__ float g_dtin[(size_t)MROWS * DTR];     // 1.0 MB

// ---------------- helpers ----------------
__device__ __forceinline__ float softplusf(float x) {
    return (x > 20.f) ? x : log1pf(__expf(x));
}

__device__ __forceinline__ uint32_t f2tf32(float x) {
    uint32_t r;
    asm("cvt.rna.tf32.f32 %0, %1;" : "=r"(r) : "f"(x));
    return r;
}

__device__ __forceinline__ uint32_t smem_u32(const void* p) {
    uint32_t a;
    asm("{ .reg .u64 t; cvta.to.shared.u64 t, %1; cvt.u32.u64 %0, t; }"
        : "=r"(a) : "l"(p));
    return a;
}

// ---------------- tf32 convert pass (bandwidth-bound) ----------------
__global__ void cvt_tf32_kernel(const float* __restrict__ src,
                                float* __restrict__ dst, int n4)
{
    int i = blockIdx.x * blockDim.x + threadIdx.x;
    if (i >= n4) return;
    float4 v = reinterpret_cast<const float4*>(src)[i];
    uint4 o = make_uint4(f2tf32(v.x), f2tf32(v.y), f2tf32(v.z), f2tf32(v.w));
    reinterpret_cast<uint4*>(dst)[i] = o;
}

// slice xdbl[:, 0:64] -> g_dtin (tf32-rounded), row stride XD -> DTR
__global__ void cvt_dtslice_kernel(const float* __restrict__ xdbl,
                                   float* __restrict__ dtin)
{
    int i = blockIdx.x * blockDim.x + threadIdx.x;   // over MROWS*16 float4s
    if (i >= MROWS * (DTR/4)) return;
    int row = i >> 4;
    int c4  = (i & 15) << 2;
    float4 v = *reinterpret_cast<const float4*>(xdbl + (size_t)row * XD + c4);
    uint4 o = make_uint4(f2tf32(v.x), f2tf32(v.y), f2tf32(v.z), f2tf32(v.w));
    *reinterpret_cast<uint4*>(dtin + (size_t)row * DTR + c4) = o;
}

// =====================================================================
// cp.async-pipelined tf32 mma GEMM: C = A(MxK) * B(NxK)^T.
// Operands MUST be pre-rounded to tf32 bit patterns.
// BM=BN=128, BK=32, 256 threads, warp tile 64x32, 3-stage smem ring.
// Requires M%128==0, N%128==0, K%32==0, K>=64.
// Smem layout: per stage A[128x32f]+B[128x32f]; 16B chunks XOR-swizzled:
//   byte(row,k) = row*128 + (((k>>2) ^ (row&7))<<4) + (k&3)*4
// ACT: 0 = none, 1 = softplus(c + bias[n])
// =====================================================================
#define GEMM_SMEM (3*32768)

template<int ACT>
__global__ void __launch_bounds__(256, 2)
gemm_ca(const float* __restrict__ A, int lda,
        const float* __restrict__ Bm, int ldb,
        float* __restrict__ C, int ldc,
        const float* __restrict__ bias, int K)
{
    extern __shared__ __align__(128) uint32_t sm[];
    const uint32_t sbase = smem_u32(sm);

    const int tid  = threadIdx.x;
    const int wid  = tid >> 5;
    const int lane = tid & 31;
    const int g    = lane >> 2;
    const int tig  = lane & 3;
    const int wm   = (wid >> 2) * 64;
    const int wn   = (wid & 3) * 32;
    const int m0   = blockIdx.y * 128;
    const int n0   = blockIdx.x * 128;

    // cp.async mapping: thread covers rows (tid>>3)+32i, chunk tid&7 (16B)
    const int rb    = tid >> 3;
    const int chk   = tid & 7;
    const uint32_t cxoff = (uint32_t)((chk ^ (rb & 7)) << 4);
    const float* gA0 = A  + (size_t)(m0 + rb) * lda + chk * 4;
    const float* gB0 = Bm + (size_t)(n0 + rb) * ldb + chk * 4;
    const uint32_t sA0 = sbase + rb * 128 + cxoff;

    const int T = K >> 5;

    auto issue_tile = [&](int t) {
        const int stage = t % 3;
        const int k0 = t << 5;
        const uint32_t sA = sA0 + stage * 32768;
        const uint32_t sB = sA + 16384;
        const float* gA = gA0 + k0;
        const float* gB = gB0 + k0;
#pragma unroll
        for (int i = 0; i < 4; i++) {
            asm volatile("cp.async.cg.shared.global [%0], [%1], 16;"
                         :: "r"(sA + i * 4096), "l"(gA + (size_t)32 * i * lda));
            asm volatile("cp.async.cg.shared.global [%0], [%1], 16;"
                         :: "r"(sB + i * 4096), "l"(gB + (size_t)32 * i * ldb));
        }
        asm volatile("cp.async.commit_group;" ::: "memory");
    };

    float c[4][4][4];
#pragma unroll
    for (int i = 0; i < 4; i++)
#pragma unroll
        for (int j = 0; j < 4; j++)
#pragma unroll
            for (int r = 0; r < 4; r++) c[i][j][r] = 0.f;

    auto compute = [&](int stage) {
        const uint32_t* Asm = sm + stage * 8192;
        const uint32_t* Bsm = Asm + 4096;
#pragma unroll
        for (int ks = 0; ks < 4; ks++) {
            const int c1 = (((2 * ks)     ^ g) << 2) + tig;  // word off, k=8ks+tig
            const int c2 = (((2 * ks + 1) ^ g) << 2) + tig;  // word off, k=8ks+tig+4
            uint32_t a[4][4], b[4][2];
#pragma unroll
            for (int mt = 0; mt < 4; mt++) {
                const int r = (wm + mt * 16 + g) << 5;
                a[mt][0] = Asm[r + c1];
                a[mt][1] = Asm[r + 256 + c1];
                a[mt][2] = Asm[r + c2];
                a[mt][3] = Asm[r + 256 + c2];
            }
#pragma unroll
            for (int nt = 0; nt < 4; nt++) {
                const int r = (wn + nt * 8 + g) << 5;
                b[nt][0] = Bsm[r + c1];
                b[nt][1] = Bsm[r + c2];
            }
#pragma unroll
            for (int mt = 0; mt < 4; mt++)
#pragma unroll
                for (int nt = 0; nt < 4; nt++) {
                    asm volatile(
                        "mma.sync.aligned.m16n8k8.row.col.f32.tf32.tf32.f32 "
                        "{%0,%1,%2,%3}, {%4,%5,%6,%7}, {%8,%9}, {%0,%1,%2,%3};\n"
                        : "+f"(c[mt][nt][0]), "+f"(c[mt][nt][1]),
                          "+f"(c[mt][nt][2]), "+f"(c[mt][nt][3])
                        : "r"(a[mt][0]), "r"(a[mt][1]), "r"(a[mt][2]), "r"(a[mt][3]),
                          "r"(b[nt][0]), "r"(b[nt][1]));
                }
        }
    };

    // prologue: tiles 0 and 1
    issue_tile(0);
    issue_tile(1);

    for (int t = 0; t < T; ++t) {
        if (t + 2 < T) {
            issue_tile(t + 2);
            asm volatile("cp.async.wait_group 2;" ::: "memory");
        } else {
            asm volatile("cp.async.wait_group 0;" ::: "memory");
        }
        __syncthreads();
        compute(t % 3);
        __syncthreads();
    }

    // ---- epilogue ----
#pragma unroll
    for (int mt = 0; mt < 4; mt++) {
        int r = m0 + wm + mt * 16 + g;
#pragma unroll
        for (int nt = 0; nt < 4; nt++) {
            int n = n0 + wn + nt * 8 + tig * 2;
            float v0 = c[mt][nt][0], v1 = c[mt][nt][1];
            float v2 = c[mt][nt][2], v3 = c[mt][nt][3];
            if (ACT == 1) {
                float b0 = bias[n], b1 = bias[n + 1];
                v0 = softplusf(v0 + b0);  v1 = softplusf(v1 + b1);
                v2 = softplusf(v2 + b0);  v3 = softplusf(v3 + b1);
            }
            *reinterpret_cast<float2*>(C + (size_t)r * ldc + n)       = make_float2(v0, v1);
            *reinterpret_cast<float2*>(C + (size_t)(r + 8) * ldc + n) = make_float2(v2, v3);
        }
    }
}

// ---------------- FFMA NT SGEMM (kept for x_proj, exact fp32) ----------------
template<int BM, int BN, int BK, int TM, int TN>
__global__ void __launch_bounds__((BM/TM)*(BN/TN))
sgemm_nt(const float* __restrict__ A, int lda,
         const float* __restrict__ Bm, int ldb,
         float* __restrict__ C, int ldc,
         int M, int N, int K)
{
    constexpr int THREADS = (BM/TM)*(BN/TN);
    constexpr int A_SLOTS = BM*BK/4;
    constexpr int B_SLOTS = BN*BK/4;

    __shared__ float As[BK][BM];
    __shared__ float Bs[BK][BN];

    const int tid = threadIdx.x;
    const int tx = tid % (BN/TN);
    const int ty = tid / (BN/TN);
    const int m0 = blockIdx.y * BM;
    const int n0 = blockIdx.x * BN;

    float acc[TM][TN];
#pragma unroll
    for (int i = 0; i < TM; i++)
#pragma unroll
        for (int j = 0; j < TN; j++) acc[i][j] = 0.f;

    for (int k0 = 0; k0 < K; k0 += BK) {
#pragma unroll
        for (int it = 0; it < A_SLOTS/THREADS; it++) {
            int s = tid + it*THREADS;
            int row = s / (BK/4);
            int kk  = (s % (BK/4)) * 4;
            float4 v = *reinterpret_cast<const float4*>(
                A + (size_t)(m0 + row) * lda + k0 + kk);
            As[kk+0][row] = v.x; As[kk+1][row] = v.y;
            As[kk+2][row] = v.z; As[kk+3][row] = v.w;
        }
#pragma unroll
        for (int it = 0; it < B_SLOTS/THREADS; it++) {
            int s = tid + it*THREADS;
            int row = s / (BK/4);
            int kk  = (s % (BK/4)) * 4;
            float4 v = make_float4(0.f, 0.f, 0.f, 0.f);
            if (n0 + row < N)
                v = *reinterpret_cast<const float4*>(
                    Bm + (size_t)(n0 + row) * ldb + k0 + kk);
            Bs[kk+0][row] = v.x; Bs[kk+1][row] = v.y;
            Bs[kk+2][row] = v.z; Bs[kk+3][row] = v.w;
        }
        __syncthreads();

#pragma unroll
        for (int kk = 0; kk < BK; kk++) {
            float a[TM], b[TN];
#pragma unroll
            for (int i = 0; i < TM; i += 4) {
                float4 v = *reinterpret_cast<const float4*>(&As[kk][ty*TM + i]);
                a[i+0] = v.x; a[i+1] = v.y; a[i+2] = v.z; a[i+3] = v.w;
            }
#pragma unroll
            for (int j = 0; j < TN; j += 4) {
                float4 v = *reinterpret_cast<const float4*>(&Bs[kk][tx*TN + j]);
                b[j+0] = v.x; b[j+1] = v.y; b[j+2] = v.z; b[j+3] = v.w;
            }
#pragma unroll
            for (int i = 0; i < TM; i++)
#pragma unroll
                for (int j = 0; j < TN; j++)
                    acc[i][j] = fmaf(a[i], b[j], acc[i][j]);
        }
        __syncthreads();
    }

#pragma unroll
    for (int i = 0; i < TM; i++) {
        int m = m0 + ty*TM + i;
#pragma unroll
        for (int j = 0; j < TN; j++) {
            int n = n0 + tx*TN + j;
            if (n < N) C[(size_t)m * ldc + n] = acc[i][j];
        }
    }
}

// ---------------- depthwise conv1d k=3 pad=1 (input = first half of xz) --------
__global__ void conv_kernel(const float* __restrict__ xz,
                            const float* __restrict__ w,
                            const float* __restrict__ bconv,
                            float* __restrict__ xc)
{
    int idx = blockIdx.x * blockDim.x + threadIdx.x;   // over MROWS*DIM
    if (idx >= MROWS * DIM) return;
    int d = idx & (DIM - 1);
    int l = (idx >> 10) & (SEQ - 1);
    const float* base = xz + (size_t)(idx >> 10) * (2*DIM) + d;
    float w0 = w[d*3+0], w1 = w[d*3+1], w2 = w[d*3+2];
    float acc = bconv[d];
    if (l > 0)       acc = fmaf(w0, base[-(2*DIM)], acc);
    acc = fmaf(w1, base[0], acc);
    if (l < SEQ - 1) acc = fmaf(w2, base[2*DIM], acc);
    xc[idx] = acc;
}

// ---------------- selective scan + D skip + SiLU(z) gate -----------------------
// One warp = 2 channels x 16 states. Output yg is tf32-rounded (feeds out_proj).
__global__ void scan_kernel(const float* __restrict__ delta,
                            const float* __restrict__ u,
                            const float* __restrict__ xdbl,
                            const float* __restrict__ xz,
                            const float* __restrict__ A_log,
                            const float* __restrict__ Dp,
                            float* __restrict__ yg)
{
    const int lane = threadIdx.x & 31;
    const int warp = threadIdx.x >> 5;
    const int n = lane & 15;
    const int chan = blockIdx.x * ((int)blockDim.x >> 4) + (warp << 1) + (lane >> 4);
    const int b = chan >> 10;          // chan / DIM
    const int d = chan & (DIM - 1);

    const float A    = -__expf(__ldg(A_log + d*NST + n));
    const float Dpar = __ldg(Dp + d);

    const size_t row0 = (size_t)b * SEQ;
    const float* pD  = delta + row0 * DIM + d;
    const float* pU  = u     + row0 * DIM + d;
    const float* pBC = xdbl  + row0 * XD;
    const float* pZ  = xz    + row0 * (2*DIM) + DIM + d;
    float*       pY  = yg    + row0 * DIM + d;

    float s = 0.f;
#pragma unroll 2
    for (int t = 0; t < SEQ; ++t) {
        float dt = __ldg(pD);
        float uu = __ldg(pU);
        float Bn = __ldg(pBC + DTR + n);
        float Cn = __ldg(pBC + DTR + NST + n);

        float dA = __expf(dt * A);
        s = fmaf(dA, s, dt * Bn * uu);

        float p = s * Cn;
        p += __shfl_xor_sync(0xffffffffu, p, 1);
        p += __shfl_xor_sync(0xffffffffu, p, 2);
        p += __shfl_xor_sync(0xffffffffu, p, 4);
        p += __shfl_xor_sync(0xffffffffu, p, 8);

        if (n == 0) {
            float z = __ldg(pZ);
            float sig = __fdividef(1.f, 1.f + __expf(-z));
            float val = fmaf(uu, Dpar, p) * (z * sig);
            pY[0] = __uint_as_float(f2tf32(val));   // tf32-ready for out_proj
        }
        pD += DIM; pU += DIM; pBC += XD; pZ += 2*DIM; pY += DIM;
    }
}

// ---------------- launcher ----------------
extern "C" void kernel_launch(void* const* d_in, const int* in_sizes, int n_in,
                              void* d_out, int out_size)
{
    const float* x          = (const float*)d_in[0];
    const float* in_proj_w  = (const float*)d_in[1];
    const float* conv_w     = (const float*)d_in[2];
    const float* conv_b     = (const float*)d_in[3];
    const float* A_log      = (const float*)d_in[4];
    const float* D_param    = (const float*)d_in[5];
    const float* x_proj_w   = (const float*)d_in[6];
    const float* dt_proj_w  = (const float*)d_in[7];
    const float* dt_proj_b  = (const float*)d_in[8];
    const float* out_proj_w = (const float*)d_in[9];
    float* out = (float*)d_out;

    float *xz, *xc, *xdbl, *delta, *yg, *xtf, *wtin, *wtout, *wtdt, *dtin;
    cudaGetSymbolAddress((void**)&xz,    g_xz);
    cudaGetSymbolAddress((void**)&xc,    g_xc);
    cudaGetSymbolAddress((void**)&xdbl,  g_xdbl);
    cudaGetSymbolAddress((void**)&delta, g_delta);
    cudaGetSymbolAddress((void**)&yg,    g_yg);
    cudaGetSymbolAddress((void**)&xtf,   g_xtf);
    cudaGetSymbolAddress((void**)&wtin,  g_wtf_in);
    cudaGetSymbolAddress((void**)&wtout, g_wtf_out);
    cudaGetSymbolAddress((void**)&wtdt,  g_wtf_dt);
    cudaGetSymbolAddress((void**)&dtin,  g_dtin);

    const int M = MROWS;

    cudaFuncSetAttribute(gemm_ca<0>, cudaFuncAttributeMaxDynamicSharedMemorySize, GEMM_SMEM);
    cudaFuncSetAttribute(gemm_ca<1>, cudaFuncAttributeMaxDynamicSharedMemorySize, GEMM_SMEM);

    // 0. tf32-round GEMM operands (bandwidth-bound passes)
    cvt_tf32_kernel<<<(M*DIM/4 + 255)/256, 256>>>(x, xtf, M*DIM/4);
    cvt_tf32_kernel<<<(2*DIM*DIM/4 + 255)/256, 256>>>(in_proj_w, wtin, 2*DIM*DIM/4);
    cvt_tf32_kernel<<<(DIM*DIM/4 + 255)/256, 256>>>(out_proj_w, wtout, DIM*DIM/4);
    cvt_tf32_kernel<<<(DIM*DTR/4 + 255)/256, 256>>>(dt_proj_w, wtdt, DIM*DTR/4);

    // 1. in_proj: xz = x @ in_proj_w^T   (4096 x 2048 x 1024)
    gemm_ca<0><<<dim3((2*DIM)/128, M/128), 256, GEMM_SMEM>>>(
        xtf, DIM, wtin, DIM, xz, 2*DIM, nullptr, DIM);

    // 2. depthwise conv1d on first half of xz -> xc
    conv_kernel<<<(M*DIM)/256, 256>>>(xz, conv_w, conv_b, xc);

    // 3. x_proj: xdbl = xc @ x_proj_w^T  (4096 x 96 x 1024)  [exact fp32]
    sgemm_nt<64,64,16,4,4><<<dim3((XD + 63)/64, M/64), 256>>>(
        xc, DIM, x_proj_w, DIM, xdbl, XD, M, XD, DIM);

    // 3b. slice + tf32-round dt_r part of xdbl
    cvt_dtslice_kernel<<<(M*(DTR/4) + 255)/256, 256>>>(xdbl, dtin);

    // 4. dt_proj + softplus: delta = softplus(dtin @ dt_proj_w^T + b)
    gemm_ca<1><<<dim3(DIM/128, M/128), 256, GEMM_SMEM>>>(
        dtin, DTR, wtdt, DTR, delta, DIM, dt_proj_b, DTR);

    // 5. selective scan + D skip + SiLU(z) gate -> yg (tf32-rounded)
    scan_kernel<<<(BATCH*DIM)/8, 128>>>(delta, xc, xdbl, xz, A_log, D_param, yg);

    // 6. out_proj: out = yg @ out_proj_w^T  (4096 x 1024 x 1024)
    gemm_ca<0><<<dim3(DIM/128, M/128), 256, GEMM_SMEM>>>(
        yg, DIM, wtout, DIM, out, DIM, nullptr, DIM);
}

// round 7
// speedup vs baseline: 2.8865x; 2.8773x over previous
#include <cuda_runtime.h>
#include <cstdint>

#define BATCH 2
#define SEQ   2048
#define DIM   1024
#define NST   16
#define DTR   64
#define XD    96   /* dt_rank + 2*N */

#define MROWS (BATCH*SEQ) /* 4096 */

#define NC 8      /* scan chunks */
#define LC 256    /* chunk length = SEQ/NC */

// ---------------- scratch (allocation-free: __device__ globals) ----------------
__device__ float g_xz[(size_t)MROWS * 2 * DIM];   // 33.5 MB
__device__ float g_xc[(size_t)MROWS * DIM];       // 16.8 MB
__device__ float g_xdbl[(size_t)MROWS * XD];      // 1.6 MB
__device__ float g_delta[(size_t)MROWS * DIM];    // 16.8 MB
__device__ float g_yg[(size_t)MROWS * DIM];       // 16.8 MB (tf32-rounded by scan)
// tf32-rounded operand copies
__device__ float g_xtf[(size_t)MROWS * DIM];      // 16.8 MB
__device__ float g_wtf_in[(size_t)2 * DIM * DIM]; // 8.4 MB
__device__ float g_wtf_out[(size_t)DIM * DIM];    // 4.2 MB
__device__ float g_wtf_dt[(size_t)DIM * DTR];     // 0.26 MB
__device__ float g_dtin[(size_t)MROWS * DTR];     // 1.0 MB
// chunked-scan chain state: layout [(b*NC + c) * DIM*NST + d*NST + n]
__device__ float g_scanP[(size_t)BATCH * NC * DIM * NST];  // 1.0 MB
__device__ float g_scanS[(size_t)BATCH * NC * DIM * NST];  // 1.0 MB
__device__ float g_scanI[(size_t)BATCH * NC * DIM * NST];  // 1.0 MB

// ---------------- helpers ----------------
__device__ __forceinline__ float softplusf(float x) {
    return (x > 20.f) ? x : log1pf(__expf(x));
}

__device__ __forceinline__ uint32_t f2tf32(float x) {
    uint32_t r;
    asm("cvt.rna.tf32.f32 %0, %1;" : "=r"(r) : "f"(x));
    return r;
}

__device__ __forceinline__ uint32_t smem_u32(const void* p) {
    uint32_t a;
    asm("{ .reg .u64 t; cvta.to.shared.u64 t, %1; cvt.u32.u64 %0, t; }"
        : "=r"(a) : "l"(p));
    return a;
}

// ---------------- tf32 convert pass (bandwidth-bound) ----------------
__global__ void cvt_tf32_kernel(const float* __restrict__ src,
                                float* __restrict__ dst, int n4)
{
    int i = blockIdx.x * blockDim.x + threadIdx.x;
    if (i >= n4) return;
    float4 v = reinterpret_cast<const float4*>(src)[i];
    uint4 o = make_uint4(f2tf32(v.x), f2tf32(v.y), f2tf32(v.z), f2tf32(v.w));
    reinterpret_cast<uint4*>(dst)[i] = o;
}

// slice xdbl[:, 0:64] -> g_dtin (tf32-rounded), row stride XD -> DTR
__global__ void cvt_dtslice_kernel(const float* __restrict__ xdbl,
                                   float* __restrict__ dtin)
{
    int i = blockIdx.x * blockDim.x + threadIdx.x;   // over MROWS*16 float4s
    if (i >= MROWS * (DTR/4)) return;
    int row = i >> 4;
    int c4  = (i & 15) << 2;
    float4 v = *reinterpret_cast<const float4*>(xdbl + (size_t)row * XD + c4);
    uint4 o = make_uint4(f2tf32(v.x), f2tf32(v.y), f2tf32(v.z), f2tf32(v.w));
    *reinterpret_cast<uint4*>(dtin + (size_t)row * DTR + c4) = o;
}

// =====================================================================
// cp.async-pipelined tf32 mma GEMM: C = A(MxK) * B(NxK)^T.
// Operands MUST be pre-rounded to tf32 bit patterns.
// BM=BN=128, BK=32, 256 threads, warp tile 64x32, 3-stage smem ring.
// ACT: 0 = none, 1 = softplus(c + bias[n])
// =====================================================================
#define GEMM_SMEM (3*32768)

template<int ACT>
__global__ void __launch_bounds__(256, 2)
gemm_ca(const float* __restrict__ A, int lda,
        const float* __restrict__ Bm, int ldb,
        float* __restrict__ C, int ldc,
        const float* __restrict__ bias, int K)
{
    extern __shared__ __align__(128) uint32_t sm[];
    const uint32_t sbase = smem_u32(sm);

    const int tid  = threadIdx.x;
    const int wid  = tid >> 5;
    const int lane = tid & 31;
    const int g    = lane >> 2;
    const int tig  = lane & 3;
    const int wm   = (wid >> 2) * 64;
    const int wn   = (wid & 3) * 32;
    const int m0   = blockIdx.y * 128;
    const int n0   = blockIdx.x * 128;

    // cp.async mapping: thread covers rows (tid>>3)+32i, chunk tid&7 (16B)
    const int rb    = tid >> 3;
    const int chk   = tid & 7;
    const uint32_t cxoff = (uint32_t)((chk ^ (rb & 7)) << 4);
    const float* gA0 = A  + (size_t)(m0 + rb) * lda + chk * 4;
    const float* gB0 = Bm + (size_t)(n0 + rb) * ldb + chk * 4;
    const uint32_t sA0 = sbase + rb * 128 + cxoff;

    const int T = K >> 5;

    auto issue_tile = [&](int t) {
        const int stage = t % 3;
        const int k0 = t << 5;
        const uint32_t sA = sA0 + stage * 32768;
        const uint32_t sB = sA + 16384;
        const float* gA = gA0 + k0;
        const float* gB = gB0 + k0;
#pragma unroll
        for (int i = 0; i < 4; i++) {
            asm volatile("cp.async.cg.shared.global [%0], [%1], 16;"
                         :: "r"(sA + i * 4096), "l"(gA + (size_t)32 * i * lda));
            asm volatile("cp.async.cg.shared.global [%0], [%1], 16;"
                         :: "r"(sB + i * 4096), "l"(gB + (size_t)32 * i * ldb));
        }
        asm volatile("cp.async.commit_group;" ::: "memory");
    };

    float c[4][4][4];
#pragma unroll
    for (int i = 0; i < 4; i++)
#pragma unroll
        for (int j = 0; j < 4; j++)
#pragma unroll
            for (int r = 0; r < 4; r++) c[i][j][r] = 0.f;

    auto compute = [&](int stage) {
        const uint32_t* Asm = sm + stage * 8192;
        const uint32_t* Bsm = Asm + 4096;
#pragma unroll
        for (int ks = 0; ks < 4; ks++) {
            const int c1 = (((2 * ks)     ^ g) << 2) + tig;  // word off, k=8ks+tig
            const int c2 = (((2 * ks + 1) ^ g) << 2) + tig;  // word off, k=8ks+tig+4
            uint32_t a[4][4], b[4][2];
#pragma unroll
            for (int mt = 0; mt < 4; mt++) {
                const int r = (wm + mt * 16 + g) << 5;
                a[mt][0] = Asm[r + c1];
                a[mt][1] = Asm[r + 256 + c1];
                a[mt][2] = Asm[r + c2];
                a[mt][3] = Asm[r + 256 + c2];
            }
#pragma unroll
            for (int nt = 0; nt < 4; nt++) {
                const int r = (wn + nt * 8 + g) << 5;
                b[nt][0] = Bsm[r + c1];
                b[nt][1] = Bsm[r + c2];
            }
#pragma unroll
            for (int mt = 0; mt < 4; mt++)
#pragma unroll
                for (int nt = 0; nt < 4; nt++) {
                    asm volatile(
                        "mma.sync.aligned.m16n8k8.row.col.f32.tf32.tf32.f32 "
                        "{%0,%1,%2,%3}, {%4,%5,%6,%7}, {%8,%9}, {%0,%1,%2,%3};\n"
                        : "+f"(c[mt][nt][0]), "+f"(c[mt][nt][1]),
                          "+f"(c[mt][nt][2]), "+f"(c[mt][nt][3])
                        : "r"(a[mt][0]), "r"(a[mt][1]), "r"(a[mt][2]), "r"(a[mt][3]),
                          "r"(b[nt][0]), "r"(b[nt][1]));
                }
        }
    };

    issue_tile(0);
    issue_tile(1);

    for (int t = 0; t < T; ++t) {
        if (t + 2 < T) {
            issue_tile(t + 2);
            asm volatile("cp.async.wait_group 2;" ::: "memory");
        } else {
            asm volatile("cp.async.wait_group 0;" ::: "memory");
        }
        __syncthreads();
        compute(t % 3);
        __syncthreads();
    }

    // ---- epilogue ----
#pragma unroll
    for (int mt = 0; mt < 4; mt++) {
        int r = m0 + wm + mt * 16 + g;
#pragma unroll
        for (int nt = 0; nt < 4; nt++) {
            int n = n0 + wn + nt * 8 + tig * 2;
            float v0 = c[mt][nt][0], v1 = c[mt][nt][1];
            float v2 = c[mt][nt][2], v3 = c[mt][nt][3];
            if (ACT == 1) {
                float b0 = bias[n], b1 = bias[n + 1];
                v0 = softplusf(v0 + b0);  v1 = softplusf(v1 + b1);
                v2 = softplusf(v2 + b0);  v3 = softplusf(v3 + b1);
            }
            *reinterpret_cast<float2*>(C + (size_t)r * ldc + n)       = make_float2(v0, v1);
            *reinterpret_cast<float2*>(C + (size_t)(r + 8) * ldc + n) = make_float2(v2, v3);
        }
    }
}

// ---------------- FFMA NT SGEMM (kept for x_proj, exact fp32) ----------------
template<int BM, int BN, int BK, int TM, int TN>
__global__ void __launch_bounds__((BM/TM)*(BN/TN))
sgemm_nt(const float* __restrict__ A, int lda,
         const float* __restrict__ Bm, int ldb,
         float* __restrict__ C, int ldc,
         int M, int N, int K)
{
    constexpr int THREADS = (BM/TM)*(BN/TN);
    constexpr int A_SLOTS = BM*BK/4;
    constexpr int B_SLOTS = BN*BK/4;

    __shared__ float As[BK][BM];
    __shared__ float Bs[BK][BN];

    const int tid = threadIdx.x;
    const int tx = tid % (BN/TN);
    const int ty = tid / (BN/TN);
    const int m0 = blockIdx.y * BM;
    const int n0 = blockIdx.x * BN;

    float acc[TM][TN];
#pragma unroll
    for (int i = 0; i < TM; i++)
#pragma unroll
        for (int j = 0; j < TN; j++) acc[i][j] = 0.f;

    for (int k0 = 0; k0 < K; k0 += BK) {
#pragma unroll
        for (int it = 0; it < A_SLOTS/THREADS; it++) {
            int s = tid + it*THREADS;
            int row = s / (BK/4);
            int kk  = (s % (BK/4)) * 4;
            float4 v = *reinterpret_cast<const float4*>(
                A + (size_t)(m0 + row) * lda + k0 + kk);
            As[kk+0][row] = v.x; As[kk+1][row] = v.y;
            As[kk+2][row] = v.z; As[kk+3][row] = v.w;
        }
#pragma unroll
        for (int it = 0; it < B_SLOTS/THREADS; it++) {
            int s = tid + it*THREADS;
            int row = s / (BK/4);
            int kk  = (s % (BK/4)) * 4;
            float4 v = make_float4(0.f, 0.f, 0.f, 0.f);
            if (n0 + row < N)
                v = *reinterpret_cast<const float4*>(
                    Bm + (size_t)(n0 + row) * ldb + k0 + kk);
            Bs[kk+0][row] = v.x; Bs[kk+1][row] = v.y;
            Bs[kk+2][row] = v.z; Bs[kk+3][row] = v.w;
        }
        __syncthreads();

#pragma unroll
        for (int kk = 0; kk < BK; kk++) {
            float a[TM], b[TN];
#pragma unroll
            for (int i = 0; i < TM; i += 4) {
                float4 v = *reinterpret_cast<const float4*>(&As[kk][ty*TM + i]);
                a[i+0] = v.x; a[i+1] = v.y; a[i+2] = v.z; a[i+3] = v.w;
            }
#pragma unroll
            for (int j = 0; j < TN; j += 4) {
                float4 v = *reinterpret_cast<const float4*>(&Bs[kk][tx*TN + j]);
                b[j+0] = v.x; b[j+1] = v.y; b[j+2] = v.z; b[j+3] = v.w;
            }
#pragma unroll
            for (int i = 0; i < TM; i++)
#pragma unroll
                for (int j = 0; j < TN; j++)
                    acc[i][j] = fmaf(a[i], b[j], acc[i][j]);
        }
        __syncthreads();
    }

#pragma unroll
    for (int i = 0; i < TM; i++) {
        int m = m0 + ty*TM + i;
#pragma unroll
        for (int j = 0; j < TN; j++) {
            int n = n0 + tx*TN + j;
            if (n < N) C[(size_t)m * ldc + n] = acc[i][j];
        }
    }
}

// ---------------- depthwise conv1d k=3 pad=1 (input = first half of xz) --------
__global__ void conv_kernel(const float* __restrict__ xz,
                            const float* __restrict__ w,
                            const float* __restrict__ bconv,
                            float* __restrict__ xc)
{
    int idx = blockIdx.x * blockDim.x + threadIdx.x;   // over MROWS*DIM
    if (idx >= MROWS * DIM) return;
    int d = idx & (DIM - 1);
    int l = (idx >> 10) & (SEQ - 1);
    const float* base = xz + (size_t)(idx >> 10) * (2*DIM) + d;
    float w0 = w[d*3+0], w1 = w[d*3+1], w2 = w[d*3+2];
    float acc = bconv[d];
    if (l > 0)       acc = fmaf(w0, base[-(2*DIM)], acc);
    acc = fmaf(w1, base[0], acc);
    if (l < SEQ - 1) acc = fmaf(w2, base[2*DIM], acc);
    xc[idx] = acc;
}

// =====================================================================
// Chunked selective scan. Recurrence s_t = dA_t * s_{t-1} + dt*B*u is
// linear, so: per-chunk (P = prod dA, S = zero-init partial state), then
// a tiny sequential chain over NC=8 chunks, then per-chunk re-emit of y
// from the exact chunk-initial state.
// Warp = 2 channels x 16 states. Lanes 0-15: chan0; 16-31: chan1.
// =====================================================================

// Pass A: per-chunk P and S (no reduction, no output)
__global__ void __launch_bounds__(256)
scan_part(const float* __restrict__ delta,
          const float* __restrict__ u,
          const float* __restrict__ xdbl,
          const float* __restrict__ A_log,
          float* __restrict__ Pout,
          float* __restrict__ Sout)
{
    const int lane = threadIdx.x & 31;
    const int warp = threadIdx.x >> 5;
    const int n = lane & 15;
    const int chan = blockIdx.x * 16 + (warp << 1) + (lane >> 4);
    const int b = chan >> 10;
    const int d = chan & (DIM - 1);
    const int c = blockIdx.y;

    const float A = -__expf(__ldg(A_log + d*NST + n));

    const size_t row0 = (size_t)b * SEQ + (size_t)c * LC;
    const float* pD  = delta + row0 * DIM + d;
    const float* pU  = u     + row0 * DIM + d;
    const float* pBC = xdbl  + row0 * XD + DTR + n;

    float s = 0.f, P = 1.f;
#pragma unroll 4
    for (int t = 0; t < LC; ++t) {
        float dt = __ldg(pD);
        float uu = __ldg(pU);
        float Bn = __ldg(pBC);
        float dA = __expf(dt * A);
        s = fmaf(dA, s, dt * Bn * uu);
        P *= dA;
        pD += DIM; pU += DIM; pBC += XD;
    }
    const size_t o = (((size_t)b * NC + c) * DIM + d) * NST + n;
    Pout[o] = P;
    Sout[o] = s;
}

// Pass B: sequential chain over chunks -> exact initial state per chunk
__global__ void __launch_bounds__(256)
scan_chain(const float* __restrict__ P,
           const float* __restrict__ S,
           float* __restrict__ I)
{
    const int tid = blockIdx.x * blockDim.x + threadIdx.x;  // 0..32767
    const int b = tid >> 14;            // / (DIM*NST)
    const int rest = tid & 16383;       // d*NST + n
    float s = 0.f;
#pragma unroll
    for (int c = 0; c < NC; ++c) {
        const size_t o = (((size_t)b * NC + c) << 14) + rest;
        I[o] = s;
        s = fmaf(P[o], s, S[o]);
    }
}

// Pass C: re-run each chunk from its initial state, emit gated y (tf32)
__global__ void __launch_bounds__(256)
scan_emit(const float* __restrict__ delta,
          const float* __restrict__ u,
          const float* __restrict__ xdbl,
          const float* __restrict__ xz,
          const float* __restrict__ A_log,
          const float* __restrict__ Dp,
          const float* __restrict__ I,
          float* __restrict__ yg)
{
    const int lane = threadIdx.x & 31;
    const int warp = threadIdx.x >> 5;
    const int n = lane & 15;
    const int chan = blockIdx.x * 16 + (warp << 1) + (lane >> 4);
    const int b = chan >> 10;
    const int d = chan & (DIM - 1);
    const int c = blockIdx.y;

    const float A    = -__expf(__ldg(A_log + d*NST + n));
    const float Dpar = __ldg(Dp + d);

    const size_t row0 = (size_t)b * SEQ + (size_t)c * LC;
    const float* pD  = delta + row0 * DIM + d;
    const float* pU  = u     + row0 * DIM + d;
    const float* pBC = xdbl  + row0 * XD;
    const float* pZ  = xz    + row0 * (2*DIM) + DIM + d;
    float*       pY  = yg    + row0 * DIM + d;

    float s = I[(((size_t)b * NC + c) * DIM + d) * NST + n];

#pragma unroll 2
    for (int t = 0; t < LC; ++t) {
        float dt = __ldg(pD);
        float uu = __ldg(pU);
        float Bn = __ldg(pBC + DTR + n);
        float Cn = __ldg(pBC + DTR + NST + n);

        float dA = __expf(dt * A);
        s = fmaf(dA, s, dt * Bn * uu);

        float p = s * Cn;
        p += __shfl_xor_sync(0xffffffffu, p, 1);
        p += __shfl_xor_sync(0xffffffffu, p, 2);
        p += __shfl_xor_sync(0xffffffffu, p, 4);
        p += __shfl_xor_sync(0xffffffffu, p, 8);

        if (n == 0) {
            float z = __ldg(pZ);
            float sig = __fdividef(1.f, 1.f + __expf(-z));
            float val = fmaf(uu, Dpar, p) * (z * sig);
            pY[0] = __uint_as_float(f2tf32(val));   // tf32-ready for out_proj
        }
        pD += DIM; pU += DIM; pBC += XD; pZ += 2*DIM; pY += DIM;
    }
}

// ---------------- launcher ----------------
extern "C" void kernel_launch(void* const* d_in, const int* in_sizes, int n_in,
                              void* d_out, int out_size)
{
    const float* x          = (const float*)d_in[0];
    const float* in_proj_w  = (const float*)d_in[1];
    const float* conv_w     = (const float*)d_in[2];
    const float* conv_b     = (const float*)d_in[3];
    const float* A_log      = (const float*)d_in[4];
    const float* D_param    = (const float*)d_in[5];
    const float* x_proj_w   = (const float*)d_in[6];
    const float* dt_proj_w  = (const float*)d_in[7];
    const float* dt_proj_b  = (const float*)d_in[8];
    const float* out_proj_w = (const float*)d_in[9];
    float* out = (float*)d_out;

    float *xz, *xc, *xdbl, *delta, *yg, *xtf, *wtin, *wtout, *wtdt, *dtin;
    float *sP, *sS, *sI;
    cudaGetSymbolAddress((void**)&xz,    g_xz);
    cudaGetSymbolAddress((void**)&xc,    g_xc);
    cudaGetSymbolAddress((void**)&xdbl,  g_xdbl);
    cudaGetSymbolAddress((void**)&delta, g_delta);
    cudaGetSymbolAddress((void**)&yg,    g_yg);
    cudaGetSymbolAddress((void**)&xtf,   g_xtf);
    cudaGetSymbolAddress((void**)&wtin,  g_wtf_in);
    cudaGetSymbolAddress((void**)&wtout, g_wtf_out);
    cudaGetSymbolAddress((void**)&wtdt,  g_wtf_dt);
    cudaGetSymbolAddress((void**)&dtin,  g_dtin);
    cudaGetSymbolAddress((void**)&sP,    g_scanP);
    cudaGetSymbolAddress((void**)&sS,    g_scanS);
    cudaGetSymbolAddress((void**)&sI,    g_scanI);

    const int M = MROWS;

    cudaFuncSetAttribute(gemm_ca<0>, cudaFuncAttributeMaxDynamicSharedMemorySize, GEMM_SMEM);
    cudaFuncSetAttribute(gemm_ca<1>, cudaFuncAttributeMaxDynamicSharedMemorySize, GEMM_SMEM);

    // 0. tf32-round GEMM operands (bandwidth-bound passes)
    cvt_tf32_kernel<<<(M*DIM/4 + 255)/256, 256>>>(x, xtf, M*DIM/4);
    cvt_tf32_kernel<<<(2*DIM*DIM/4 + 255)/256, 256>>>(in_proj_w, wtin, 2*DIM*DIM/4);
    cvt_tf32_kernel<<<(DIM*DIM/4 + 255)/256, 256>>>(out_proj_w, wtout, DIM*DIM/4);
    cvt_tf32_kernel<<<(DIM*DTR/4 + 255)/256, 256>>>(dt_proj_w, wtdt, DIM*DTR/4);

    // 1. in_proj: xz = x @ in_proj_w^T   (4096 x 2048 x 1024)
    gemm_ca<0><<<dim3((2*DIM)/128, M/128), 256, GEMM_SMEM>>>(
        xtf, DIM, wtin, DIM, xz, 2*DIM, nullptr, DIM);

    // 2. depthwise conv1d on first half of xz -> xc
    conv_kernel<<<(M*DIM)/256, 256>>>(xz, conv_w, conv_b, xc);

    // 3. x_proj: xdbl = xc @ x_proj_w^T  (4096 x 96 x 1024)  [exact fp32]
    sgemm_nt<64,64,16,4,4><<<dim3((XD + 63)/64, M/64), 256>>>(
        xc, DIM, x_proj_w, DIM, xdbl, XD, M, XD, DIM);

    // 3b. slice + tf32-round dt_r part of xdbl
    cvt_dtslice_kernel<<<(M*(DTR/4) + 255)/256, 256>>>(xdbl, dtin);

    // 4. dt_proj + softplus: delta = softplus(dtin @ dt_proj_w^T + b)
    gemm_ca<1><<<dim3(DIM/128, M/128), 256, GEMM_SMEM>>>(
        dtin, DTR, wtdt, DTR, delta, DIM, dt_proj_b, DTR);

    // 5. chunked selective scan (parallelism x8 over time chunks)
    scan_part<<<dim3((BATCH*DIM)/16, NC), 256>>>(delta, xc, xdbl, A_log, sP, sS);
    scan_chain<<<(BATCH*DIM*NST)/256, 256>>>(sP, sS, sI);
    scan_emit<<<dim3((BATCH*DIM)/16, NC), 256>>>(delta, xc, xdbl, xz, A_log,
                                                 D_param, sI, yg);

    // 6. out_proj: out = yg @ out_proj_w^T  (4096 x 1024 x 1024)
    gemm_ca<0><<<dim3(DIM/128, M/128), 256, GEMM_SMEM>>>(
        yg, DIM, wtout, DIM, out, DIM, nullptr, DIM);
}